// round 4
// baseline (speedup 1.0000x reference)
#include <cuda_runtime.h>
#include <cuda_bf16.h>
#include <math.h>
#include <stdint.h>

// MoE dims (fixed)
#define NT 16384
#define DD 512
#define HH 2048
#define EE 8
#define KK 2
#define CAP 8192                 // per-expert row capacity (avg load = 4096)
#define CROWS (CAP * EE)         // 65536 scratch rows

// ---------------- device scratch ----------------
__device__ __nv_bfloat16 g_x_hi[(size_t)NT * DD];
__device__ __nv_bfloat16 g_x_lo[(size_t)NT * DD];
__device__ __nv_bfloat16 g_w1t_hi[(size_t)EE * HH * DD];  // [e][h][d]
__device__ __nv_bfloat16 g_w1t_lo[(size_t)EE * HH * DD];
__device__ __nv_bfloat16 g_w2t_hi[(size_t)EE * DD * HH];  // [e][d][h]
__device__ __nv_bfloat16 g_w2t_lo[(size_t)EE * DD * HH];
__device__ __nv_bfloat16 g_h_hi[(size_t)CROWS * HH];
__device__ __nv_bfloat16 g_h_lo[(size_t)CROWS * HH];
__device__ float g_y[(size_t)CROWS * DD];
__device__ int   g_perm[CROWS];
__device__ int   g_rowOf[NT * KK];
__device__ float g_gate2[NT * KK];
__device__ int   g_topi[NT * KK];
__device__ float g_topv[NT * KK];
__device__ int   g_fill[EE];

__device__ __forceinline__ uint32_t smem_u32(const void* p) {
    uint32_t a;
    asm("{ .reg .u64 t; cvta.to.shared.u64 t, %1; cvt.u32.u64 %0, t; }" : "=r"(a) : "l"(p));
    return a;
}
__device__ __forceinline__ void cp16(uint32_t saddr, const void* gaddr, uint32_t sz) {
    asm volatile("cp.async.ca.shared.global [%0], [%1], 16, %2;"
                 :: "r"(saddr), "l"(gaddr), "r"(sz) : "memory");
}
#define CP_COMMIT() asm volatile("cp.async.commit_group;" ::: "memory")

__device__ __forceinline__ void ldsm_x4(uint32_t* r, uint32_t addr) {
    asm volatile("ldmatrix.sync.aligned.m8n8.x4.shared.b16 {%0,%1,%2,%3}, [%4];"
                 : "=r"(r[0]), "=r"(r[1]), "=r"(r[2]), "=r"(r[3]) : "r"(addr));
}
__device__ __forceinline__ void mma16816(float* c, const uint32_t* a, const uint32_t* b) {
    asm volatile(
        "mma.sync.aligned.m16n8k16.row.col.f32.bf16.bf16.f32 "
        "{%0,%1,%2,%3}, {%4,%5,%6,%7}, {%8,%9}, {%0,%1,%2,%3};"
        : "+f"(c[0]), "+f"(c[1]), "+f"(c[2]), "+f"(c[3])
        : "r"(a[0]), "r"(a[1]), "r"(a[2]), "r"(a[3]), "r"(b[0]), "r"(b[1]));
}
__device__ __forceinline__ void split_bf16(float v, __nv_bfloat16& hi, __nv_bfloat16& lo) {
    hi = __float2bfloat16(v);
    lo = __float2bfloat16(v - __bfloat162float(hi));
}

// ---------------- prep: zero counters + convert x + transpose/split W1,W2 ----------------
// blocks [0,8192): convert x    [8192,16384): W1    [16384,24576): W2
__global__ __launch_bounds__(256)
void prep_kernel(const float* __restrict__ x,
                 const float* __restrict__ W1,
                 const float* __restrict__ W2) {
    __shared__ float t[32][33];
    const int b = blockIdx.x;
    const int tid = threadIdx.x;

    if (b < 8192) {
        if (b == 0 && tid < EE) g_fill[tid] = 0;
        int i = b * 256 + tid;             // exactly NT*DD/4 elements
        float4 v = ((const float4*)x)[i];
        __nv_bfloat16 h0, h1, h2, h3, l0, l1, l2, l3;
        split_bf16(v.x, h0, l0); split_bf16(v.y, h1, l1);
        split_bf16(v.z, h2, l2); split_bf16(v.w, h3, l3);
        __nv_bfloat162* H = (__nv_bfloat162*)g_x_hi;
        __nv_bfloat162* L = (__nv_bfloat162*)g_x_lo;
        H[i * 2 + 0] = __nv_bfloat162(h0, h1); H[i * 2 + 1] = __nv_bfloat162(h2, h3);
        L[i * 2 + 0] = __nv_bfloat162(l0, l1); L[i * 2 + 1] = __nv_bfloat162(l2, l3);
        return;
    }

    const bool isW1 = (b < 16384);
    const int  bb   = isW1 ? (b - 8192) : (b - 16384);
    const int  R    = isW1 ? DD : HH;     // src rows
    const int  C    = isW1 ? HH : DD;     // src cols
    const int  CB   = C / 32;
    const int  e    = bb / (CB * (R / 32));
    const int  rem  = bb % (CB * (R / 32));
    const int  cb   = rem % CB;
    const int  rb   = rem / CB;
    const int  c0 = cb * 32, r0 = rb * 32;
    const int  tx = tid & 31, ty = tid >> 5;

    const float* s = (isW1 ? W1 : W2) + (size_t)e * R * C;
    __nv_bfloat16* dh = (isW1 ? g_w1t_hi : g_w2t_hi) + (size_t)e * R * C;
    __nv_bfloat16* dl = (isW1 ? g_w1t_lo : g_w2t_lo) + (size_t)e * R * C;

#pragma unroll
    for (int i = 0; i < 4; i++)
        t[ty + i * 8][tx] = s[(size_t)(r0 + ty + i * 8) * C + c0 + tx];
    __syncthreads();
#pragma unroll
    for (int i = 0; i < 4; i++) {
        float v = t[tx][ty + i * 8];
        __nv_bfloat16 hi, lo; split_bf16(v, hi, lo);
        size_t o = (size_t)(c0 + ty + i * 8) * R + r0 + tx;
        dh[o] = hi; dl[o] = lo;
    }
}

// ---------------- router (one warp per token) ----------------
__global__ __launch_bounds__(256)
void router_kernel(const float* __restrict__ x, const float* __restrict__ Wr) {
    __shared__ float sWrT[EE * DD];
    int tid = threadIdx.x;
    for (int i = tid; i < DD * EE; i += blockDim.x) {
        int d = i / EE, e = i % EE;
        sWrT[e * DD + d] = Wr[i];
    }
    __syncthreads();
    int warp = tid >> 5, lane = tid & 31;
    int n = blockIdx.x * 8 + warp;
    if (n >= NT) return;
    float acc[EE];
#pragma unroll
    for (int e = 0; e < EE; e++) acc[e] = 0.f;
    const float* xr = x + (size_t)n * DD;
#pragma unroll
    for (int it = 0; it < DD / 32; it++) {
        float xv = xr[lane + it * 32];
#pragma unroll
        for (int e = 0; e < EE; e++) acc[e] += xv * sWrT[e * DD + lane + it * 32];
    }
#pragma unroll
    for (int e = 0; e < EE; e++)
#pragma unroll
        for (int s = 16; s > 0; s >>= 1)
            acc[e] += __shfl_xor_sync(0xffffffffu, acc[e], s);
    if (lane == 0) {
        float m = acc[0];
#pragma unroll
        for (int e = 1; e < EE; e++) m = fmaxf(m, acc[e]);
        float p[EE], s = 0.f;
#pragma unroll
        for (int e = 0; e < EE; e++) { p[e] = expf(acc[e] - m); s += p[e]; }
        float inv = 1.f / s;
        int i1 = 0; float v1 = p[0];
#pragma unroll
        for (int e = 1; e < EE; e++) if (p[e] > v1) { v1 = p[e]; i1 = e; }
        int i2 = -1; float v2 = -1.f;
#pragma unroll
        for (int e = 0; e < EE; e++) if (e != i1 && p[e] > v2) { v2 = p[e]; i2 = e; }
        g_topi[2 * n + 0] = i1; g_topv[2 * n + 0] = v1 * inv;
        g_topi[2 * n + 1] = i2; g_topv[2 * n + 1] = v2 * inv;
    }
}

// ---------------- scatter into fixed-capacity expert segments ----------------
__global__ void scatter_kernel() {
    int i = blockIdx.x * blockDim.x + threadIdx.x;
    if (i >= NT * KK) return;
    int token = i >> 1;
    int e = g_topi[i];
    int pos = atomicAdd(&g_fill[e], 1);
    int row = e * CAP + pos;
    g_perm[row] = token;
    g_rowOf[i] = row;
    g_gate2[i] = g_topv[i];
}

// ---------------- HMMA GEMM: 128x128 tile, K-chunk 32, 4-stage cp.async ----------------
#define ROWB 80
#define ARR_BYTES (128 * ROWB)
#define STAGE_BYTES (4 * ARR_BYTES)
#define NSTAGE 4
#define SMEM_GEMM_BYTES (NSTAGE * STAGE_BYTES)

template <bool FC1>
__global__ __launch_bounds__(256)
void moe_gemm_hmma_kernel(const float* __restrict__ bias) {
    constexpr int Kd = FC1 ? DD : HH;
    constexpr int Nd = FC1 ? HH : DD;
    constexpr int NCHUNK = Kd / 32;

    extern __shared__ char smem[];
    const int e = blockIdx.z;
    const int cnt = g_fill[e];
    const int m0 = blockIdx.y * 128;
    if (m0 >= cnt) return;
    const int off = e * CAP;
    const int n0 = blockIdx.x * 128;
    const int tid = threadIdx.x;
    const int wid = tid >> 5, lane = tid & 31;

    const __nv_bfloat16* aH = FC1 ? g_x_hi : g_h_hi;
    const __nv_bfloat16* aL = FC1 ? g_x_lo : g_h_lo;
    const __nv_bfloat16* wH = FC1 ? g_w1t_hi : g_w2t_hi;
    const __nv_bfloat16* wL = FC1 ? g_w1t_lo : g_w2t_lo;

    // staging: thread -> (row = tid/2, 2 of 4 16B segments)
    const int srow = tid >> 1;
    const int part = tid & 1;
    long long arow;
    {
        int m = m0 + srow;
        if (m < cnt) arow = FC1 ? (long long)g_perm[off + m] * DD
                                : (long long)(off + m) * HH;
        else arow = -1;
    }
    const size_t brow = ((size_t)e * Nd + n0 + srow) * Kd;

    const uint32_t sb = smem_u32(smem);
    const uint32_t rowoff = srow * ROWB + part * 32;
    const uint32_t aok = (arow >= 0) ? 16u : 0u;
    const __nv_bfloat16* pah = aH + (arow >= 0 ? arow : 0);
    const __nv_bfloat16* pal = aL + (arow >= 0 ? arow : 0);
    const __nv_bfloat16* pbh = wH + brow;
    const __nv_bfloat16* pbl = wL + brow;

    auto stage = [&](int c) {
        const uint32_t so = (uint32_t)(c & (NSTAGE - 1)) * STAGE_BYTES + rowoff;
        const int k0 = c * 32 + part * 16;
#pragma unroll
        for (int i = 0; i < 2; i++) {
            int ke = k0 + i * 8;            // element offset; 16B per cp
            cp16(sb + so                 + i * 16, pah + ke, aok);
            cp16(sb + so +     ARR_BYTES + i * 16, pal + ke, aok);
            cp16(sb + so + 2 * ARR_BYTES + i * 16, pbh + ke, 16u);
            cp16(sb + so + 3 * ARR_BYTES + i * 16, pbl + ke, 16u);
        }
        CP_COMMIT();
    };

    // ldmatrix lane addressing
    const int warpM = (wid >> 2) * 64;
    const int warpN = (wid & 3) * 32;
    const int g = lane >> 3, lr = lane & 7;
    const uint32_t aLaneOff = (uint32_t)(warpM + lr + ((g & 1) << 3)) * ROWB + ((g >> 1) << 4);
    const uint32_t bLaneOff = (uint32_t)(warpN + lr + ((g >> 1) << 3)) * ROWB + ((g & 1) << 4);

    float acc[4][4][4];
#pragma unroll
    for (int i = 0; i < 4; i++)
#pragma unroll
        for (int j = 0; j < 4; j++)
#pragma unroll
            for (int k = 0; k < 4; k++) acc[i][j][k] = 0.f;

    stage(0);
    if (NCHUNK > 1) stage(1);
    if (NCHUNK > 2) stage(2);

#pragma unroll 1
    for (int c = 0; c < NCHUNK; c++) {
        if (c + 2 < NCHUNK)      asm volatile("cp.async.wait_group 2;" ::: "memory");
        else if (c + 1 < NCHUNK) asm volatile("cp.async.wait_group 1;" ::: "memory");
        else                     asm volatile("cp.async.wait_group 0;" ::: "memory");
        __syncthreads();
        if (c + 3 < NCHUNK) stage(c + 3);   // overlap next-stage loads with compute

        const uint32_t st = (uint32_t)(c & (NSTAGE - 1)) * STAGE_BYTES;
        const uint32_t sA_hi = sb + st;
        const uint32_t sA_lo = sA_hi + ARR_BYTES;
        const uint32_t sB_hi = sA_hi + 2 * ARR_BYTES;
        const uint32_t sB_lo = sA_hi + 3 * ARR_BYTES;
#pragma unroll
        for (int ks = 0; ks < 2; ks++) {
            const uint32_t ko = ks * 32;
            uint32_t bh[4][4], bl[4][4];
            ldsm_x4(bh[0], sB_hi + ko + bLaneOff);
            ldsm_x4(bh[2], sB_hi + ko + bLaneOff + 16 * ROWB);
            ldsm_x4(bl[0], sB_lo + ko + bLaneOff);
            ldsm_x4(bl[2], sB_lo + ko + bLaneOff + 16 * ROWB);
#pragma unroll
            for (int mt = 0; mt < 4; mt++) {
                uint32_t ah[4], al[4];
                ldsm_x4(ah, sA_hi + ko + aLaneOff + mt * 16 * ROWB);
                ldsm_x4(al, sA_lo + ko + aLaneOff + mt * 16 * ROWB);
#pragma unroll
                for (int nf = 0; nf < 4; nf++) {
                    const uint32_t* BH = &bh[(nf >> 1) * 2][(nf & 1) * 2];
                    const uint32_t* BL = &bl[(nf >> 1) * 2][(nf & 1) * 2];
                    mma16816(acc[mt][nf], ah, BH);
                    mma16816(acc[mt][nf], ah, BL);
                    mma16816(acc[mt][nf], al, BH);
                }
            }
        }
    }

    // epilogue
    const int rr = lane >> 2;
    const int cc2 = (lane & 3) * 2;
    float bv[4][2];
#pragma unroll
    for (int nf = 0; nf < 4; nf++) {
        int col = n0 + warpN + nf * 8 + cc2;
        bv[nf][0] = __ldg(&bias[(size_t)e * Nd + col]);
        bv[nf][1] = __ldg(&bias[(size_t)e * Nd + col + 1]);
    }
#pragma unroll
    for (int mt = 0; mt < 4; mt++) {
#pragma unroll
        for (int nf = 0; nf < 4; nf++) {
            int col = n0 + warpN + nf * 8 + cc2;
#pragma unroll
            for (int h = 0; h < 2; h++) {
                int m = m0 + warpM + mt * 16 + rr + h * 8;
                if (m < cnt) {
                    float v0 = acc[mt][nf][h * 2 + 0] + bv[nf][0];
                    float v1 = acc[mt][nf][h * 2 + 1] + bv[nf][1];
                    size_t orow = (size_t)(off + m);
                    if (FC1) {
                        v0 = fmaxf(v0, 0.f); v1 = fmaxf(v1, 0.f);
                        __nv_bfloat16 h0, l0, h1, l1;
                        split_bf16(v0, h0, l0); split_bf16(v1, h1, l1);
                        *(__nv_bfloat162*)(g_h_hi + orow * HH + col) = __nv_bfloat162(h0, h1);
                        *(__nv_bfloat162*)(g_h_lo + orow * HH + col) = __nv_bfloat162(l0, l1);
                    } else {
                        *(float2*)(g_y + orow * DD + col) = make_float2(v0, v1);
                    }
                }
            }
        }
    }
}

// ---------------- combine ----------------
__global__ __launch_bounds__(128)
void combine_kernel(float* __restrict__ out) {
    int n = blockIdx.x;
    int d = threadIdx.x * 4;
    int r0 = g_rowOf[2 * n + 0];
    int r1 = g_rowOf[2 * n + 1];
    float g0 = g_gate2[2 * n + 0];
    float g1 = g_gate2[2 * n + 1];
    float4 y0 = *(const float4*)&g_y[(size_t)r0 * DD + d];
    float4 y1 = *(const float4*)&g_y[(size_t)r1 * DD + d];
    float4 o;
    o.x = g0 * y0.x + g1 * y1.x;
    o.y = g0 * y0.y + g1 * y1.y;
    o.z = g0 * y0.z + g1 * y1.z;
    o.w = g0 * y0.w + g1 * y1.w;
    *(float4*)&out[(size_t)n * DD + d] = o;
}

__global__ void tail_kernel(float* __restrict__ out, long long start, long long total) {
    long long i = start + (long long)blockIdx.x * blockDim.x + threadIdx.x;
    if (i < total) out[i] = 0.f;
}

extern "C" void kernel_launch(void* const* d_in, const int* in_sizes, int n_in,
                              void* d_out, int out_size) {
    const float* x  = (const float*)d_in[0];
    const float* Wr = (const float*)d_in[1];
    const float* W1 = (const float*)d_in[2];
    const float* b1 = (const float*)d_in[3];
    const float* W2 = (const float*)d_in[4];
    const float* b2 = (const float*)d_in[5];
    float* out = (float*)d_out;

    cudaFuncSetAttribute(moe_gemm_hmma_kernel<true>,
                         cudaFuncAttributeMaxDynamicSharedMemorySize, SMEM_GEMM_BYTES);
    cudaFuncSetAttribute(moe_gemm_hmma_kernel<false>,
                         cudaFuncAttributeMaxDynamicSharedMemorySize, SMEM_GEMM_BYTES);

    prep_kernel<<<24576, 256>>>(x, W1, W2);                       // 0
    router_kernel<<<NT / 8, 256>>>(x, Wr);                        // 1
    scatter_kernel<<<(NT * KK + 255) / 256, 256>>>();             // 2
    moe_gemm_hmma_kernel<true ><<<dim3(HH / 128, CAP / 128, EE),  // 3 <- ncu profiles this
                                  256, SMEM_GEMM_BYTES>>>(b1);
    moe_gemm_hmma_kernel<false><<<dim3(DD / 128, CAP / 128, EE),  // 4
                                  256, SMEM_GEMM_BYTES>>>(b2);
    combine_kernel<<<NT, 128>>>(out);                             // 5

    long long main_elems = (long long)NT * DD;
    long long total = (long long)out_size;
    if (total > main_elems) {
        long long tail = total - main_elems;
        int blocks = (int)((tail + 255) / 256);
        tail_kernel<<<blocks, 256>>>(out, main_elems, total);
    }
}

// round 5
// speedup vs baseline: 1.5058x; 1.5058x over previous
#include <cuda_runtime.h>
#include <cuda_fp16.h>
#include <math.h>
#include <stdint.h>

// MoE dims (fixed)
#define NT 16384
#define DD 512
#define HH 2048
#define EE 8
#define KK 2
#define CAP 8192
#define CROWS (CAP * EE)

// ---------------- device scratch ----------------
__device__ __half g_x_hi[(size_t)NT * DD];
__device__ __half g_x_lo[(size_t)NT * DD];
__device__ __half g_w1t[(size_t)EE * HH * DD];   // [e][h][d] fp16 (hi only)
__device__ __half g_w2t[(size_t)EE * DD * HH];   // [e][d][h] fp16 (hi only)
__device__ __half g_h_hi[(size_t)CROWS * HH];
__device__ __half g_h_lo[(size_t)CROWS * HH];
__device__ float g_y[(size_t)CROWS * DD];
__device__ int   g_perm[CROWS];
__device__ int   g_rowOf[NT * KK];
__device__ float g_gate2[NT * KK];
__device__ int   g_topi[NT * KK];
__device__ float g_topv[NT * KK];
__device__ int   g_fill[EE];

__device__ __forceinline__ uint32_t smem_u32(const void* p) {
    uint32_t a;
    asm("{ .reg .u64 t; cvta.to.shared.u64 t, %1; cvt.u32.u64 %0, t; }" : "=r"(a) : "l"(p));
    return a;
}
__device__ __forceinline__ void cp16(uint32_t saddr, const void* gaddr, uint32_t sz) {
    asm volatile("cp.async.ca.shared.global [%0], [%1], 16, %2;"
                 :: "r"(saddr), "l"(gaddr), "r"(sz) : "memory");
}
#define CP_COMMIT() asm volatile("cp.async.commit_group;" ::: "memory")

__device__ __forceinline__ void ldsm_x4(uint32_t* r, uint32_t addr) {
    asm volatile("ldmatrix.sync.aligned.m8n8.x4.shared.b16 {%0,%1,%2,%3}, [%4];"
                 : "=r"(r[0]), "=r"(r[1]), "=r"(r[2]), "=r"(r[3]) : "r"(addr));
}
__device__ __forceinline__ void mma16816(float* c, const uint32_t* a, const uint32_t* b) {
    asm volatile(
        "mma.sync.aligned.m16n8k16.row.col.f32.f16.f16.f32 "
        "{%0,%1,%2,%3}, {%4,%5,%6,%7}, {%8,%9}, {%0,%1,%2,%3};"
        : "+f"(c[0]), "+f"(c[1]), "+f"(c[2]), "+f"(c[3])
        : "r"(a[0]), "r"(a[1]), "r"(a[2]), "r"(a[3]), "r"(b[0]), "r"(b[1]));
}
__device__ __forceinline__ void split_f16(float v, __half& hi, __half& lo) {
    hi = __float2half_rn(v);
    lo = __float2half_rn(v - __half2float(hi));
}

// ---------------- prep: zero counters + convert x(hi/lo) + transpose W1,W2 (fp16 hi) ----
// blocks [0,8192): x    [8192,16384): W1    [16384,24576): W2
__global__ __launch_bounds__(256)
void prep_kernel(const float* __restrict__ x,
                 const float* __restrict__ W1,
                 const float* __restrict__ W2) {
    __shared__ float t[32][33];
    const int b = blockIdx.x;
    const int tid = threadIdx.x;

    if (b < 8192) {
        if (b == 0 && tid < EE) g_fill[tid] = 0;
        int i = b * 256 + tid;
        float4 v = ((const float4*)x)[i];
        __half h0, h1, h2, h3, l0, l1, l2, l3;
        split_f16(v.x, h0, l0); split_f16(v.y, h1, l1);
        split_f16(v.z, h2, l2); split_f16(v.w, h3, l3);
        __half2* H = (__half2*)g_x_hi;
        __half2* L = (__half2*)g_x_lo;
        H[i * 2 + 0] = __halves2half2(h0, h1); H[i * 2 + 1] = __halves2half2(h2, h3);
        L[i * 2 + 0] = __halves2half2(l0, l1); L[i * 2 + 1] = __halves2half2(l2, l3);
        return;
    }

    const bool isW1 = (b < 16384);
    const int  bb   = isW1 ? (b - 8192) : (b - 16384);
    const int  R    = isW1 ? DD : HH;
    const int  C    = isW1 ? HH : DD;
    const int  CB   = C / 32;
    const int  e    = bb / (CB * (R / 32));
    const int  rem  = bb % (CB * (R / 32));
    const int  cb   = rem % CB;
    const int  rb   = rem / CB;
    const int  c0 = cb * 32, r0 = rb * 32;
    const int  tx = tid & 31, ty = tid >> 5;

    const float* s = (isW1 ? W1 : W2) + (size_t)e * R * C;
    __half* dh = (isW1 ? g_w1t : g_w2t) + (size_t)e * R * C;

#pragma unroll
    for (int i = 0; i < 4; i++)
        t[ty + i * 8][tx] = s[(size_t)(r0 + ty + i * 8) * C + c0 + tx];
    __syncthreads();
#pragma unroll
    for (int i = 0; i < 4; i++) {
        float v = t[tx][ty + i * 8];
        dh[(size_t)(c0 + ty + i * 8) * R + r0 + tx] = __float2half_rn(v);
    }
}

// ---------------- router ----------------
__global__ __launch_bounds__(256)
void router_kernel(const float* __restrict__ x, const float* __restrict__ Wr) {
    __shared__ float sWrT[EE * DD];
    int tid = threadIdx.x;
    for (int i = tid; i < DD * EE; i += blockDim.x) {
        int d = i / EE, e = i % EE;
        sWrT[e * DD + d] = Wr[i];
    }
    __syncthreads();
    int warp = tid >> 5, lane = tid & 31;
    int n = blockIdx.x * 8 + warp;
    if (n >= NT) return;
    float acc[EE];
#pragma unroll
    for (int e = 0; e < EE; e++) acc[e] = 0.f;
    const float* xr = x + (size_t)n * DD;
#pragma unroll
    for (int it = 0; it < DD / 32; it++) {
        float xv = xr[lane + it * 32];
#pragma unroll
        for (int e = 0; e < EE; e++) acc[e] += xv * sWrT[e * DD + lane + it * 32];
    }
#pragma unroll
    for (int e = 0; e < EE; e++)
#pragma unroll
        for (int s = 16; s > 0; s >>= 1)
            acc[e] += __shfl_xor_sync(0xffffffffu, acc[e], s);
    if (lane == 0) {
        float m = acc[0];
#pragma unroll
        for (int e = 1; e < EE; e++) m = fmaxf(m, acc[e]);
        float p[EE], s = 0.f;
#pragma unroll
        for (int e = 0; e < EE; e++) { p[e] = expf(acc[e] - m); s += p[e]; }
        float inv = 1.f / s;
        int i1 = 0; float v1 = p[0];
#pragma unroll
        for (int e = 1; e < EE; e++) if (p[e] > v1) { v1 = p[e]; i1 = e; }
        int i2 = -1; float v2 = -1.f;
#pragma unroll
        for (int e = 0; e < EE; e++) if (e != i1 && p[e] > v2) { v2 = p[e]; i2 = e; }
        g_topi[2 * n + 0] = i1; g_topv[2 * n + 0] = v1 * inv;
        g_topi[2 * n + 1] = i2; g_topv[2 * n + 1] = v2 * inv;
    }
}

__global__ void scatter_kernel() {
    int i = blockIdx.x * blockDim.x + threadIdx.x;
    if (i >= NT * KK) return;
    int token = i >> 1;
    int e = g_topi[i];
    int pos = atomicAdd(&g_fill[e], 1);
    int row = e * CAP + pos;
    g_perm[row] = token;
    g_rowOf[i] = row;
    g_gate2[i] = g_topv[i];
}

// ---------------- HMMA GEMM: 128x128 tile, K-chunk 32, 3-stage, fp16 2-MMA ----------------
#define ROWB 80
#define ARR_BYTES (128 * ROWB)
#define STAGE_BYTES (3 * ARR_BYTES)     // Ah, Al, Bh
#define NSTAGE 3
#define SMEM_GEMM_BYTES (NSTAGE * STAGE_BYTES)   // 92160

template <bool FC1>
__global__ __launch_bounds__(256, 2)
void moe_gemm_hmma_kernel(const float* __restrict__ bias) {
    constexpr int Kd = FC1 ? DD : HH;
    constexpr int Nd = FC1 ? HH : DD;
    constexpr int NCHUNK = Kd / 32;

    extern __shared__ char smem[];
    const int e = blockIdx.z;
    const int cnt = g_fill[e];
    const int m0 = blockIdx.y * 128;
    if (m0 >= cnt) return;
    const int off = e * CAP;
    const int n0 = blockIdx.x * 128;
    const int tid = threadIdx.x;
    const int wid = tid >> 5, lane = tid & 31;

    const __half* aH = FC1 ? g_x_hi : g_h_hi;
    const __half* aL = FC1 ? g_x_lo : g_h_lo;
    const __half* wB = FC1 ? g_w1t : g_w2t;

    // staging: thread -> row = tid/2, 2 of 4 16B segments per array
    const int srow = tid >> 1;
    const int part = tid & 1;
    long long arow;
    {
        int m = m0 + srow;
        if (m < cnt) arow = FC1 ? (long long)g_perm[off + m] * DD
                                : (long long)(off + m) * HH;
        else arow = -1;
    }
    const size_t brow = ((size_t)e * Nd + n0 + srow) * Kd;

    const uint32_t sb = smem_u32(smem);
    const uint32_t rowoff = srow * ROWB + part * 32;
    const uint32_t aok = (arow >= 0) ? 16u : 0u;
    const __half* pah = aH + (arow >= 0 ? arow : 0);
    const __half* pal = aL + (arow >= 0 ? arow : 0);
    const __half* pbh = wB + brow;

    auto stage = [&](int c) {
        int sidx = c % NSTAGE;
        const uint32_t so = (uint32_t)sidx * STAGE_BYTES + rowoff;
        const int k0 = c * 32 + part * 16;
#pragma unroll
        for (int i = 0; i < 2; i++) {
            int ke = k0 + i * 8;
            cp16(sb + so                 + i * 16, pah + ke, aok);
            cp16(sb + so +     ARR_BYTES + i * 16, pal + ke, aok);
            cp16(sb + so + 2 * ARR_BYTES + i * 16, pbh + ke, 16u);
        }
        CP_COMMIT();
    };

    // warp grid: 4 (M) x 2 (N); warp tile 32x64
    const int warpM = (wid >> 1) * 32;
    const int warpN = (wid & 1) * 64;
    const int g = lane >> 3, lr = lane & 7;
    const uint32_t aLaneOff = (uint32_t)(warpM + lr + ((g & 1) << 3)) * ROWB + ((g >> 1) << 4);
    const uint32_t bLaneOff = (uint32_t)(warpN + lr + ((g >> 1) << 3)) * ROWB + ((g & 1) << 4);

    float acc[2][8][4];
#pragma unroll
    for (int i = 0; i < 2; i++)
#pragma unroll
        for (int j = 0; j < 8; j++)
#pragma unroll
            for (int k = 0; k < 4; k++) acc[i][j][k] = 0.f;

    stage(0);
    if (NCHUNK > 1) stage(1);

#pragma unroll 1
    for (int c = 0; c < NCHUNK; c++) {
        if (c + 1 < NCHUNK) asm volatile("cp.async.wait_group 1;" ::: "memory");
        else                asm volatile("cp.async.wait_group 0;" ::: "memory");
        __syncthreads();
        if (c + 2 < NCHUNK) stage(c + 2);

        const uint32_t st = (uint32_t)(c % NSTAGE) * STAGE_BYTES;
        const uint32_t sA_hi = sb + st;
        const uint32_t sA_lo = sA_hi + ARR_BYTES;
        const uint32_t sB_hi = sA_hi + 2 * ARR_BYTES;
#pragma unroll
        for (int ks = 0; ks < 2; ks++) {
            const uint32_t ko = ks * 32;
            uint32_t bh[16];
#pragma unroll
            for (int t = 0; t < 4; t++)
                ldsm_x4(bh + 4 * t, sB_hi + ko + bLaneOff + t * 16 * ROWB);
            uint32_t ah[8], al[8];
#pragma unroll
            for (int mt = 0; mt < 2; mt++) {
                ldsm_x4(ah + 4 * mt, sA_hi + ko + aLaneOff + mt * 16 * ROWB);
                ldsm_x4(al + 4 * mt, sA_lo + ko + aLaneOff + mt * 16 * ROWB);
            }
#pragma unroll
            for (int mt = 0; mt < 2; mt++) {
#pragma unroll
                for (int nf = 0; nf < 8; nf++) {
                    const uint32_t* B = &bh[4 * (nf >> 1) + 2 * (nf & 1)];
                    mma16816(acc[mt][nf], ah + 4 * mt, B);
                    mma16816(acc[mt][nf], al + 4 * mt, B);
                }
            }
        }
    }

    // epilogue
    const int rr = lane >> 2;
    const int cc2 = (lane & 3) * 2;
    float bv[8][2];
#pragma unroll
    for (int nf = 0; nf < 8; nf++) {
        int col = n0 + warpN + nf * 8 + cc2;
        bv[nf][0] = __ldg(&bias[(size_t)e * Nd + col]);
        bv[nf][1] = __ldg(&bias[(size_t)e * Nd + col + 1]);
    }
#pragma unroll
    for (int mt = 0; mt < 2; mt++) {
#pragma unroll
        for (int nf = 0; nf < 8; nf++) {
            int col = n0 + warpN + nf * 8 + cc2;
#pragma unroll
            for (int h = 0; h < 2; h++) {
                int m = m0 + warpM + mt * 16 + rr + h * 8;
                if (m < cnt) {
                    float v0 = acc[mt][nf][h * 2 + 0] + bv[nf][0];
                    float v1 = acc[mt][nf][h * 2 + 1] + bv[nf][1];
                    size_t orow = (size_t)(off + m);
                    if (FC1) {
                        v0 = fmaxf(v0, 0.f); v1 = fmaxf(v1, 0.f);
                        __half h0, l0, h1, l1;
                        split_f16(v0, h0, l0); split_f16(v1, h1, l1);
                        *(__half2*)(g_h_hi + orow * HH + col) = __halves2half2(h0, h1);
                        *(__half2*)(g_h_lo + orow * HH + col) = __halves2half2(l0, l1);
                    } else {
                        *(float2*)(g_y + orow * DD + col) = make_float2(v0, v1);
                    }
                }
            }
        }
    }
}

// ---------------- combine ----------------
__global__ __launch_bounds__(128)
void combine_kernel(float* __restrict__ out) {
    int n = blockIdx.x;
    int d = threadIdx.x * 4;
    int r0 = g_rowOf[2 * n + 0];
    int r1 = g_rowOf[2 * n + 1];
    float g0 = g_gate2[2 * n + 0];
    float g1 = g_gate2[2 * n + 1];
    float4 y0 = *(const float4*)&g_y[(size_t)r0 * DD + d];
    float4 y1 = *(const float4*)&g_y[(size_t)r1 * DD + d];
    float4 o;
    o.x = g0 * y0.x + g1 * y1.x;
    o.y = g0 * y0.y + g1 * y1.y;
    o.z = g0 * y0.z + g1 * y1.z;
    o.w = g0 * y0.w + g1 * y1.w;
    *(float4*)&out[(size_t)n * DD + d] = o;
}

__global__ void tail_kernel(float* __restrict__ out, long long start, long long total) {
    long long i = start + (long long)blockIdx.x * blockDim.x + threadIdx.x;
    if (i < total) out[i] = 0.f;
}

extern "C" void kernel_launch(void* const* d_in, const int* in_sizes, int n_in,
                              void* d_out, int out_size) {
    const float* x  = (const float*)d_in[0];
    const float* Wr = (const float*)d_in[1];
    const float* W1 = (const float*)d_in[2];
    const float* b1 = (const float*)d_in[3];
    const float* W2 = (const float*)d_in[4];
    const float* b2 = (const float*)d_in[5];
    float* out = (float*)d_out;

    cudaFuncSetAttribute(moe_gemm_hmma_kernel<true>,
                         cudaFuncAttributeMaxDynamicSharedMemorySize, SMEM_GEMM_BYTES);
    cudaFuncSetAttribute(moe_gemm_hmma_kernel<false>,
                         cudaFuncAttributeMaxDynamicSharedMemorySize, SMEM_GEMM_BYTES);

    prep_kernel<<<24576, 256>>>(x, W1, W2);                       // 0
    router_kernel<<<NT / 8, 256>>>(x, Wr);                        // 1
    scatter_kernel<<<(NT * KK + 255) / 256, 256>>>();             // 2
    moe_gemm_hmma_kernel<true ><<<dim3(HH / 128, CAP / 128, EE),  // 3 <- ncu target
                                  256, SMEM_GEMM_BYTES>>>(b1);
    moe_gemm_hmma_kernel<false><<<dim3(DD / 128, CAP / 128, EE),  // 4
                                  256, SMEM_GEMM_BYTES>>>(b2);
    combine_kernel<<<NT, 128>>>(out);                             // 5

    long long main_elems = (long long)NT * DD;
    long long total = (long long)out_size;
    if (total > main_elems) {
        long long tail = total - main_elems;
        int blocks = (int)((tail + 255) / 256);
        tail_kernel<<<blocks, 256>>>(out, main_elems, total);
    }
}

// round 6
// speedup vs baseline: 2.3638x; 1.5698x over previous
#include <cuda_runtime.h>
#include <cuda_fp16.h>
#include <math.h>
#include <stdint.h>

// MoE dims (fixed)
#define NT 16384
#define DD 512
#define HH 2048
#define EE 8
#define KK 2
#define CAP 8192
#define CROWS (CAP * EE)

// ---------------- device scratch ----------------
__device__ __half g_x16[(size_t)NT * DD];
__device__ __half g_w1t[(size_t)EE * HH * DD];   // [e][h][d] fp16
__device__ __half g_w2t[(size_t)EE * DD * HH];   // [e][d][h] fp16
__device__ __half g_h16[(size_t)CROWS * HH];
__device__ float g_y[(size_t)CROWS * DD];
__device__ int   g_perm[CROWS];
__device__ int   g_rowOf[NT * KK];
__device__ float g_gate2[NT * KK];
__device__ int   g_topi[NT * KK];
__device__ float g_topv[NT * KK];
__device__ int   g_fill[EE];

__device__ __forceinline__ uint32_t smem_u32(const void* p) {
    uint32_t a;
    asm("{ .reg .u64 t; cvta.to.shared.u64 t, %1; cvt.u32.u64 %0, t; }" : "=r"(a) : "l"(p));
    return a;
}
__device__ __forceinline__ void cp16(uint32_t saddr, const void* gaddr, uint32_t sz) {
    asm volatile("cp.async.ca.shared.global [%0], [%1], 16, %2;"
                 :: "r"(saddr), "l"(gaddr), "r"(sz) : "memory");
}
#define CP_COMMIT() asm volatile("cp.async.commit_group;" ::: "memory")

__device__ __forceinline__ void ldsm_x4(uint32_t* r, uint32_t addr) {
    asm volatile("ldmatrix.sync.aligned.m8n8.x4.shared.b16 {%0,%1,%2,%3}, [%4];"
                 : "=r"(r[0]), "=r"(r[1]), "=r"(r[2]), "=r"(r[3]) : "r"(addr));
}
__device__ __forceinline__ void mma16816(float* c, const uint32_t* a, const uint32_t* b) {
    asm volatile(
        "mma.sync.aligned.m16n8k16.row.col.f32.f16.f16.f32 "
        "{%0,%1,%2,%3}, {%4,%5,%6,%7}, {%8,%9}, {%0,%1,%2,%3};"
        : "+f"(c[0]), "+f"(c[1]), "+f"(c[2]), "+f"(c[3])
        : "r"(a[0]), "r"(a[1]), "r"(a[2]), "r"(a[3]), "r"(b[0]), "r"(b[1]));
}

// ---------------- prep: zero counters + convert x + transpose W1,W2 (fp16) ----
// blocks [0,8192): x    [8192,16384): W1    [16384,24576): W2
__global__ __launch_bounds__(256)
void prep_kernel(const float* __restrict__ x,
                 const float* __restrict__ W1,
                 const float* __restrict__ W2) {
    __shared__ float t[32][33];
    const int b = blockIdx.x;
    const int tid = threadIdx.x;

    if (b < 8192) {
        if (b == 0 && tid < EE) g_fill[tid] = 0;
        int i = b * 256 + tid;
        float4 v = ((const float4*)x)[i];
        __half2* H = (__half2*)g_x16;
        H[i * 2 + 0] = __halves2half2(__float2half_rn(v.x), __float2half_rn(v.y));
        H[i * 2 + 1] = __halves2half2(__float2half_rn(v.z), __float2half_rn(v.w));
        return;
    }

    const bool isW1 = (b < 16384);
    const int  bb   = isW1 ? (b - 8192) : (b - 16384);
    const int  R    = isW1 ? DD : HH;
    const int  C    = isW1 ? HH : DD;
    const int  CB   = C / 32;
    const int  e    = bb / (CB * (R / 32));
    const int  rem  = bb % (CB * (R / 32));
    const int  cb   = rem % CB;
    const int  rb   = rem / CB;
    const int  c0 = cb * 32, r0 = rb * 32;
    const int  tx = tid & 31, ty = tid >> 5;

    const float* s = (isW1 ? W1 : W2) + (size_t)e * R * C;
    __half* dh = (isW1 ? g_w1t : g_w2t) + (size_t)e * R * C;

#pragma unroll
    for (int i = 0; i < 4; i++)
        t[ty + i * 8][tx] = s[(size_t)(r0 + ty + i * 8) * C + c0 + tx];
    __syncthreads();
#pragma unroll
    for (int i = 0; i < 4; i++)
        dh[(size_t)(c0 + ty + i * 8) * R + r0 + tx] = __float2half_rn(t[tx][ty + i * 8]);
}

// ---------------- router ----------------
__global__ __launch_bounds__(256)
void router_kernel(const float* __restrict__ x, const float* __restrict__ Wr) {
    __shared__ float sWrT[EE * DD];
    int tid = threadIdx.x;
    for (int i = tid; i < DD * EE; i += blockDim.x) {
        int d = i / EE, e = i % EE;
        sWrT[e * DD + d] = Wr[i];
    }
    __syncthreads();
    int warp = tid >> 5, lane = tid & 31;
    int n = blockIdx.x * 8 + warp;
    if (n >= NT) return;
    float acc[EE];
#pragma unroll
    for (int e = 0; e < EE; e++) acc[e] = 0.f;
    const float* xr = x + (size_t)n * DD;
#pragma unroll
    for (int it = 0; it < DD / 32; it++) {
        float xv = xr[lane + it * 32];
#pragma unroll
        for (int e = 0; e < EE; e++) acc[e] += xv * sWrT[e * DD + lane + it * 32];
    }
#pragma unroll
    for (int e = 0; e < EE; e++)
#pragma unroll
        for (int s = 16; s > 0; s >>= 1)
            acc[e] += __shfl_xor_sync(0xffffffffu, acc[e], s);
    if (lane == 0) {
        float m = acc[0];
#pragma unroll
        for (int e = 1; e < EE; e++) m = fmaxf(m, acc[e]);
        float p[EE], s = 0.f;
#pragma unroll
        for (int e = 0; e < EE; e++) { p[e] = expf(acc[e] - m); s += p[e]; }
        float inv = 1.f / s;
        int i1 = 0; float v1 = p[0];
#pragma unroll
        for (int e = 1; e < EE; e++) if (p[e] > v1) { v1 = p[e]; i1 = e; }
        int i2 = -1; float v2 = -1.f;
#pragma unroll
        for (int e = 0; e < EE; e++) if (e != i1 && p[e] > v2) { v2 = p[e]; i2 = e; }
        g_topi[2 * n + 0] = i1; g_topv[2 * n + 0] = v1 * inv;
        g_topi[2 * n + 1] = i2; g_topv[2 * n + 1] = v2 * inv;
    }
}

__global__ void scatter_kernel() {
    int i = blockIdx.x * blockDim.x + threadIdx.x;
    if (i >= NT * KK) return;
    int token = i >> 1;
    int e = g_topi[i];
    int pos = atomicAdd(&g_fill[e], 1);
    int row = e * CAP + pos;
    g_perm[row] = token;
    g_rowOf[i] = row;
    g_gate2[i] = g_topv[i];
}

// ---------------- HMMA GEMM: 128x128 tile, K-chunk 32, 4-stage, pure fp16 ----------------
#define ROWB 80
#define ARR_BYTES (128 * ROWB)          // 10240
#define STAGE_BYTES (2 * ARR_BYTES)     // A, B : 20480
#define NSTAGE 4
#define SMEM_GEMM_BYTES (NSTAGE * STAGE_BYTES)   // 81920

template <bool FC1>
__global__ __launch_bounds__(256, 2)
void moe_gemm_hmma_kernel(const float* __restrict__ bias) {
    constexpr int Kd = FC1 ? DD : HH;
    constexpr int Nd = FC1 ? HH : DD;
    constexpr int NCHUNK = Kd / 32;

    extern __shared__ char smem[];
    const int e = blockIdx.z;
    const int cnt = g_fill[e];
    const int m0 = blockIdx.y * 128;
    if (m0 >= cnt) return;
    const int off = e * CAP;
    const int n0 = blockIdx.x * 128;
    const int tid = threadIdx.x;
    const int wid = tid >> 5, lane = tid & 31;

    const __half* aP = FC1 ? g_x16 : g_h16;
    const __half* wB = FC1 ? g_w1t : g_w2t;

    // staging: thread -> row = tid/2, 2 of 4 16B segments per array
    const int srow = tid >> 1;
    const int part = tid & 1;
    long long arow;
    {
        int m = m0 + srow;
        if (m < cnt) arow = FC1 ? (long long)g_perm[off + m] * DD
                                : (long long)(off + m) * HH;
        else arow = -1;
    }
    const size_t brow = ((size_t)e * Nd + n0 + srow) * Kd;

    const uint32_t sb = smem_u32(smem);
    const uint32_t rowoff = srow * ROWB + part * 32;
    const uint32_t aok = (arow >= 0) ? 16u : 0u;
    const __half* pah = aP + (arow >= 0 ? arow : 0);
    const __half* pbh = wB + brow;

    auto stage = [&](int c) {
        const uint32_t so = (uint32_t)(c & (NSTAGE - 1)) * STAGE_BYTES + rowoff;
        const int k0 = c * 32 + part * 16;
#pragma unroll
        for (int i = 0; i < 2; i++) {
            int ke = k0 + i * 8;
            cp16(sb + so             + i * 16, pah + ke, aok);
            cp16(sb + so + ARR_BYTES + i * 16, pbh + ke, 16u);
        }
        CP_COMMIT();
    };

    // warp grid: 4 (M) x 2 (N); warp tile 32x64
    const int warpM = (wid >> 1) * 32;
    const int warpN = (wid & 1) * 64;
    const int g = lane >> 3, lr = lane & 7;
    const uint32_t aLaneOff = (uint32_t)(warpM + lr + ((g & 1) << 3)) * ROWB + ((g >> 1) << 4);
    const uint32_t bLaneOff = (uint32_t)(warpN + lr + ((g >> 1) << 3)) * ROWB + ((g & 1) << 4);

    float acc[2][8][4];
#pragma unroll
    for (int i = 0; i < 2; i++)
#pragma unroll
        for (int j = 0; j < 8; j++)
#pragma unroll
            for (int k = 0; k < 4; k++) acc[i][j][k] = 0.f;

    stage(0);
    if (NCHUNK > 1) stage(1);
    if (NCHUNK > 2) stage(2);

#pragma unroll 1
    for (int c = 0; c < NCHUNK; c++) {
        if (c + 2 < NCHUNK)      asm volatile("cp.async.wait_group 2;" ::: "memory");
        else if (c + 1 < NCHUNK) asm volatile("cp.async.wait_group 1;" ::: "memory");
        else                     asm volatile("cp.async.wait_group 0;" ::: "memory");
        __syncthreads();
        if (c + 3 < NCHUNK) stage(c + 3);

        const uint32_t st = (uint32_t)(c & (NSTAGE - 1)) * STAGE_BYTES;
        const uint32_t sA = sb + st;
        const uint32_t sB = sA + ARR_BYTES;
#pragma unroll
        for (int ks = 0; ks < 2; ks++) {
            const uint32_t ko = ks * 32;
            uint32_t bh[16];
#pragma unroll
            for (int t = 0; t < 4; t++)
                ldsm_x4(bh + 4 * t, sB + ko + bLaneOff + t * 16 * ROWB);
            uint32_t ah[8];
#pragma unroll
            for (int mt = 0; mt < 2; mt++)
                ldsm_x4(ah + 4 * mt, sA + ko + aLaneOff + mt * 16 * ROWB);
#pragma unroll
            for (int mt = 0; mt < 2; mt++) {
#pragma unroll
                for (int nf = 0; nf < 8; nf++) {
                    const uint32_t* B = &bh[4 * (nf >> 1) + 2 * (nf & 1)];
                    mma16816(acc[mt][nf], ah + 4 * mt, B);
                }
            }
        }
    }

    // epilogue
    const int rr = lane >> 2;
    const int cc2 = (lane & 3) * 2;
    float bv[8][2];
#pragma unroll
    for (int nf = 0; nf < 8; nf++) {
        int col = n0 + warpN + nf * 8 + cc2;
        bv[nf][0] = __ldg(&bias[(size_t)e * Nd + col]);
        bv[nf][1] = __ldg(&bias[(size_t)e * Nd + col + 1]);
    }
#pragma unroll
    for (int mt = 0; mt < 2; mt++) {
#pragma unroll
        for (int nf = 0; nf < 8; nf++) {
            int col = n0 + warpN + nf * 8 + cc2;
#pragma unroll
            for (int h = 0; h < 2; h++) {
                int m = m0 + warpM + mt * 16 + rr + h * 8;
                if (m < cnt) {
                    float v0 = acc[mt][nf][h * 2 + 0] + bv[nf][0];
                    float v1 = acc[mt][nf][h * 2 + 1] + bv[nf][1];
                    size_t orow = (size_t)(off + m);
                    if (FC1) {
                        v0 = fmaxf(v0, 0.f); v1 = fmaxf(v1, 0.f);
                        *(__half2*)(g_h16 + orow * HH + col) =
                            __halves2half2(__float2half_rn(v0), __float2half_rn(v1));
                    } else {
                        *(float2*)(g_y + orow * DD + col) = make_float2(v0, v1);
                    }
                }
            }
        }
    }
}

// ---------------- combine ----------------
__global__ __launch_bounds__(128)
void combine_kernel(float* __restrict__ out) {
    int n = blockIdx.x;
    int d = threadIdx.x * 4;
    int r0 = g_rowOf[2 * n + 0];
    int r1 = g_rowOf[2 * n + 1];
    float g0 = g_gate2[2 * n + 0];
    float g1 = g_gate2[2 * n + 1];
    float4 y0 = *(const float4*)&g_y[(size_t)r0 * DD + d];
    float4 y1 = *(const float4*)&g_y[(size_t)r1 * DD + d];
    float4 o;
    o.x = g0 * y0.x + g1 * y1.x;
    o.y = g0 * y0.y + g1 * y1.y;
    o.z = g0 * y0.z + g1 * y1.z;
    o.w = g0 * y0.w + g1 * y1.w;
    *(float4*)&out[(size_t)n * DD + d] = o;
}

__global__ void tail_kernel(float* __restrict__ out, long long start, long long total) {
    long long i = start + (long long)blockIdx.x * blockDim.x + threadIdx.x;
    if (i < total) out[i] = 0.f;
}

extern "C" void kernel_launch(void* const* d_in, const int* in_sizes, int n_in,
                              void* d_out, int out_size) {
    const float* x  = (const float*)d_in[0];
    const float* Wr = (const float*)d_in[1];
    const float* W1 = (const float*)d_in[2];
    const float* b1 = (const float*)d_in[3];
    const float* W2 = (const float*)d_in[4];
    const float* b2 = (const float*)d_in[5];
    float* out = (float*)d_out;

    cudaFuncSetAttribute(moe_gemm_hmma_kernel<true>,
                         cudaFuncAttributeMaxDynamicSharedMemorySize, SMEM_GEMM_BYTES);
    cudaFuncSetAttribute(moe_gemm_hmma_kernel<false>,
                         cudaFuncAttributeMaxDynamicSharedMemorySize, SMEM_GEMM_BYTES);

    prep_kernel<<<24576, 256>>>(x, W1, W2);                       // 0
    router_kernel<<<NT / 8, 256>>>(x, Wr);                        // 1
    scatter_kernel<<<(NT * KK + 255) / 256, 256>>>();             // 2
    moe_gemm_hmma_kernel<true ><<<dim3(HH / 128, CAP / 128, EE),  // 3 <- ncu target
                                  256, SMEM_GEMM_BYTES>>>(b1);
    moe_gemm_hmma_kernel<false><<<dim3(DD / 128, CAP / 128, EE),  // 4
                                  256, SMEM_GEMM_BYTES>>>(b2);
    combine_kernel<<<NT, 128>>>(out);                             // 5

    long long main_elems = (long long)NT * DD;
    long long total = (long long)out_size;
    if (total > main_elems) {
        long long tail = total - main_elems;
        int blocks = (int)((tail + 255) / 256);
        tail_kernel<<<blocks, 256>>>(out, main_elems, total);
    }
}